// round 8
// baseline (speedup 1.0000x reference)
#include <cuda_runtime.h>
#include <cuda_fp16.h>
#include <cuda_bf16.h>
#include <cstdint>

// ---------------- problem constants ----------------
#define L_SEQ 512
#define B_N   256
#define E_DIM 128
#define H_DIM 128
#define G4    512     // 4*H
#define T_TAG 48
#define NB    8       // batch lanes per LSTM CTA (mma N=8)

typedef unsigned long long ull;

// ---------------- scratch (device globals; no allocation allowed) ----------------
__device__ float g_xproj_f[(size_t)L_SEQ * B_N * G4];   // 256 MiB
__device__ float g_xproj_b[(size_t)L_SEQ * B_N * G4];   // 256 MiB
__device__ float g_hcat[(size_t)L_SEQ * B_N * 256];     // 128 MiB  [l][b][2H]
__device__ float g_emis[(size_t)L_SEQ * B_N * T_TAG];   // 24 MiB
__device__ float g_llh[B_N];

// ---------------- generic helpers ----------------
__device__ __forceinline__ float tanh_fast(float x) {
    float y;
    asm("tanh.approx.f32 %0, %1;" : "=f"(y) : "f"(x));
    return y;
}
__device__ __forceinline__ float sig_fast(float x) {
    return fmaf(0.5f, tanh_fast(0.5f * x), 0.5f);
}
__device__ __forceinline__ uint32_t smem_u32(const void* p) {
    uint32_t a;
    asm("{ .reg .u64 t; cvta.to.shared.u64 t, %1; cvt.u32.u64 %0, t; }" : "=r"(a) : "l"(p));
    return a;
}
__device__ __forceinline__ uint32_t bf2(float x, float y) {
    __nv_bfloat162 t = __floats2bfloat162_rn(x, y);
    return *(uint32_t*)&t;
}
__device__ __forceinline__ void mma_bf16(float* d, const uint32_t* a, const uint32_t* b) {
    asm volatile(
        "mma.sync.aligned.m16n8k16.row.col.f32.bf16.bf16.f32 "
        "{%0,%1,%2,%3}, {%4,%5,%6,%7}, {%8,%9}, {%0,%1,%2,%3};"
        : "+f"(d[0]), "+f"(d[1]), "+f"(d[2]), "+f"(d[3])
        : "r"(a[0]), "r"(a[1]), "r"(a[2]), "r"(a[3]), "r"(b[0]), "r"(b[1]));
}
__device__ __forceinline__ void ldmatrix_x2_trans(uint32_t* r, uint32_t addr) {
    asm volatile("ldmatrix.sync.aligned.m8n8.x2.trans.shared.b16 {%0,%1}, [%2];"
                 : "=r"(r[0]), "=r"(r[1]) : "r"(addr));
}
__device__ __forceinline__ void ldsm_x4(uint32_t* r, uint32_t a) {
    asm volatile("ldmatrix.sync.aligned.m8n8.x4.shared.b16 {%0,%1,%2,%3}, [%4];"
                 : "=r"(r[0]), "=r"(r[1]), "=r"(r[2]), "=r"(r[3]) : "r"(a));
}
__device__ __forceinline__ void ldsm_x2(uint32_t* r, uint32_t a) {
    asm volatile("ldmatrix.sync.aligned.m8n8.x2.shared.b16 {%0,%1}, [%2];"
                 : "=r"(r[0]), "=r"(r[1]) : "r"(a));
}
__device__ __forceinline__ void cp16(uint32_t dst, const void* src) {
    asm volatile("cp.async.ca.shared.global [%0], [%1], 16;" :: "r"(dst), "l"(src));
}

// ============================================================================
// Kernel 1: xproj = emb[words] @ Wih^T + (bih+bhh) via HMMA bf16.
// One CTA owns 128 rows and ALL 512 gates: A tile loaded once (gather),
// B streamed in 4 chunks of 128 gates through one smem buffer.
// ============================================================================
#define XPM_A_OFF    0
#define XPM_B_OFF    (128 * 136 * 2)
#define XPM_BIAS_OFF (2 * 128 * 136 * 2)
#define XPM_SMEM     (XPM_BIAS_OFF + 512 * 4)

__global__ __launch_bounds__(256) void xproj_mma_kernel(
    const int* __restrict__ words, const float* __restrict__ emb,
    const float* __restrict__ Wih_f, const float* __restrict__ bih_f,
    const float* __restrict__ bhh_f, const float* __restrict__ Wih_b,
    const float* __restrict__ bih_b, const float* __restrict__ bhh_b) {
    extern __shared__ char xsm[];
    __nv_bfloat16* A_s = (__nv_bfloat16*)(xsm + XPM_A_OFF);   // [128][136]
    __nv_bfloat16* B_s = (__nv_bfloat16*)(xsm + XPM_B_OFF);   // [128][136]
    float* bias_s      = (float*)(xsm + XPM_BIAS_OFF);        // [512]

    const int dir = blockIdx.y;
    const float* Wih = dir ? Wih_b : Wih_f;
    const float* b1  = dir ? bih_b : bih_f;
    const float* b2  = dir ? bhh_b : bhh_f;
    float* out       = dir ? g_xproj_b : g_xproj_f;

    const int row0 = blockIdx.x * 128;
    const int tid  = threadIdx.x;

    bias_s[tid]       = b1[tid] + b2[tid];
    bias_s[tid + 256] = b1[tid + 256] + b2[tid + 256];

    // A: gathered embedding rows -> bf16 [r][k], 136-elem row pad
    {
        const int r = tid >> 1, hf = tid & 1;
        const int grow = row0 + r;
        const int l = grow >> 8, b = grow & 255;
        const int w = words[b * L_SEQ + l];
        const float4* src = (const float4*)(emb + (size_t)w * E_DIM + hf * 64);
        __nv_bfloat16* dst = A_s + r * 136 + hf * 64;
#pragma unroll
        for (int i = 0; i < 8; ++i) {
            float4 v0 = src[2 * i], v1 = src[2 * i + 1];
            uint4 pk;
            pk.x = bf2(v0.x, v0.y);
            pk.y = bf2(v0.z, v0.w);
            pk.z = bf2(v1.x, v1.y);
            pk.w = bf2(v1.z, v1.w);
            *(uint4*)(dst + i * 8) = pk;
        }
    }

    const uint32_t As = smem_u32(A_s), Bs = smem_u32(B_s);
    const int lane = tid & 31, wid = tid >> 5;
    const int m_base = (wid >> 1) * 32;   // 4 m-warps
    const int n_base = (wid & 1) * 64;    // 2 n-warps

    const int aq = lane >> 3;
    const uint32_t a_row = (uint32_t)((aq & 1) * 8 + (lane & 7));
    const uint32_t a_col = (uint32_t)((aq >> 1) * 16);
    const uint32_t b_row = (uint32_t)(lane & 7);
    const uint32_t b_col = (uint32_t)(((lane >> 3) & 1) * 16);
    const int r_out = lane >> 2, c_out = (lane & 3) * 2;

    for (int nc = 0; nc < 4; ++nc) {
        const int n0 = nc * 128;
        __syncthreads();   // protect B_s from previous-iteration readers
        // B chunk: Wih rows (native [gate][k]) -> bf16 [n][k]
        {
            const int r = tid >> 1, hf = tid & 1;
            const float4* src = (const float4*)(Wih + (size_t)(n0 + r) * E_DIM + hf * 64);
            __nv_bfloat16* dst = B_s + r * 136 + hf * 64;
#pragma unroll
            for (int i = 0; i < 8; ++i) {
                float4 v0 = src[2 * i], v1 = src[2 * i + 1];
                uint4 pk;
                pk.x = bf2(v0.x, v0.y);
                pk.y = bf2(v0.z, v0.w);
                pk.z = bf2(v1.x, v1.y);
                pk.w = bf2(v1.z, v1.w);
                *(uint4*)(dst + i * 8) = pk;
            }
        }
        __syncthreads();

        float d[2][8][4];
#pragma unroll
        for (int mt = 0; mt < 2; ++mt)
#pragma unroll
            for (int nt = 0; nt < 8; ++nt)
#pragma unroll
                for (int c = 0; c < 4; ++c) d[mt][nt][c] = 0.f;

#pragma unroll
        for (int ks = 0; ks < 8; ++ks) {
            uint32_t a0[4], a1[4];
            ldsm_x4(a0, As + (m_base + 0 + a_row) * 272 + ks * 32 + a_col);
            ldsm_x4(a1, As + (m_base + 16 + a_row) * 272 + ks * 32 + a_col);
#pragma unroll
            for (int nt = 0; nt < 8; ++nt) {
                uint32_t bb[2];
                ldsm_x2(bb, Bs + (n_base + nt * 8 + b_row) * 272 + ks * 32 + b_col);
                mma_bf16(d[0][nt], a0, bb);
                mma_bf16(d[1][nt], a1, bb);
            }
        }

#pragma unroll
        for (int mt = 0; mt < 2; ++mt) {
            const int gr = row0 + m_base + mt * 16 + r_out;
#pragma unroll
            for (int nt = 0; nt < 8; ++nt) {
                const int gc = n_base + nt * 8 + c_out;
                const float bx = bias_s[n0 + gc], by = bias_s[n0 + gc + 1];
                float2 o0 = make_float2(d[mt][nt][0] + bx, d[mt][nt][1] + by);
                float2 o1 = make_float2(d[mt][nt][2] + bx, d[mt][nt][3] + by);
                *(float2*)(out + (size_t)gr * G4 + n0 + gc) = o0;
                *(float2*)(out + (size_t)(gr + 8) * G4 + n0 + gc) = o1;
            }
        }
    }
}

// ============================================================================
// Kernel 2: HMMA LSTM. 256 threads, 8 batch/CTA, Whh A-frags in registers.
// xproj staged via cp.async 3-buffer pipeline. (unchanged from R7)
// ============================================================================
#define LSTM_HBUF   0
#define LSTM_XBUF   4096
#define LSTM_SMEM   (4096 + 3 * 8 * 516 * 4)
#define XB_STRIDE   516
#define XB_BUFSZ    (8 * XB_STRIDE)

__global__ __launch_bounds__(256) void lstm_mma_kernel(const float* __restrict__ Whh_f,
                                                       const float* __restrict__ Whh_b) {
    extern __shared__ char smraw[];
    uint32_t* hbuf = (uint32_t*)(smraw + LSTM_HBUF);   // [2][128][4 bf16x2]
    float* xbuf    = (float*)(smraw + LSTM_XBUF);      // [3][8][516]

    const int tid  = threadIdx.x;
    const int lane = tid & 31;
    const int wid  = tid >> 5;
    const int gid  = lane >> 2;
    const int tig  = lane & 3;
    const int dir  = blockIdx.y;
    const int b0   = blockIdx.x * NB;
    const float* Whh = dir ? Whh_b : Whh_f;
    const float* xp  = dir ? g_xproj_b : g_xproj_f;
    float* hout      = g_hcat + dir * 128;

    const uint32_t hb_u32 = smem_u32(hbuf);
    const uint32_t xb_u32 = smem_u32(xbuf);

    uint32_t afr[4][8][4];
#pragma unroll
    for (int q = 0; q < 4; ++q) {
        const int r0 = 16 * wid + 128 * q + gid;
#pragma unroll
        for (int ks = 0; ks < 8; ++ks) {
            const int cc = ks * 16 + 2 * tig;
            float2 v00 = *(const float2*)(Whh + (size_t)r0 * 128 + cc);
            float2 v10 = *(const float2*)(Whh + (size_t)(r0 + 8) * 128 + cc);
            float2 v01 = *(const float2*)(Whh + (size_t)r0 * 128 + cc + 8);
            float2 v11 = *(const float2*)(Whh + (size_t)(r0 + 8) * 128 + cc + 8);
            afr[q][ks][0] = bf2(v00.x, v00.y);
            afr[q][ks][1] = bf2(v10.x, v10.y);
            afr[q][ks][2] = bf2(v01.x, v01.y);
            afr[q][ks][3] = bf2(v11.x, v11.y);
        }
    }

    for (int i = tid; i < 2 * 128 * 4; i += 256) hbuf[i] = 0;

#pragma unroll
    for (int ps = 0; ps < 2; ++ps) {
        const int l = dir ? (L_SEQ - 1 - ps) : ps;
        const float* src = xp + ((size_t)l * B_N + b0) * G4;
#pragma unroll
        for (int rr = 0; rr < 4; ++rr) {
            int idx = tid + rr * 256;
            int brow = idx >> 7, c16 = idx & 127;
            cp16(xb_u32 + (uint32_t)(ps * XB_BUFSZ * 4 + brow * XB_STRIDE * 4 + c16 * 16),
                 src + brow * 512 + c16 * 4);
        }
        asm volatile("cp.async.commit_group;");
    }
    asm volatile("cp.async.wait_group 1;");
    __syncthreads();

    float cst[4] = {0.f, 0.f, 0.f, 0.f};

    for (int s = 0; s < L_SEQ; ++s) {
        const int l = dir ? (L_SEQ - 1 - s) : s;

        if (s + 2 < L_SEQ) {
            const int lf = dir ? (L_SEQ - 3 - s) : (s + 2);
            const float* src = xp + ((size_t)lf * B_N + b0) * G4;
            const uint32_t dbase = xb_u32 + (uint32_t)(((s + 2) % 3) * XB_BUFSZ * 4);
#pragma unroll
            for (int rr = 0; rr < 4; ++rr) {
                int idx = tid + rr * 256;
                int brow = idx >> 7, c16 = idx & 127;
                cp16(dbase + (uint32_t)(brow * XB_STRIDE * 4 + c16 * 16),
                     src + brow * 512 + c16 * 4);
            }
            asm volatile("cp.async.commit_group;");
        }

        uint32_t rb[8][2];
        const uint32_t base = hb_u32 + (uint32_t)((s & 1) * 2048) + ((uint32_t)(lane & 15) << 4);
#pragma unroll
        for (int ks = 0; ks < 8; ++ks) ldmatrix_x2_trans(rb[ks], base + ks * 256);

        float d[4][4];
#pragma unroll
        for (int q = 0; q < 4; ++q)
#pragma unroll
            for (int c = 0; c < 4; ++c) d[q][c] = 0.f;
#pragma unroll
        for (int ks = 0; ks < 8; ++ks)
#pragma unroll
            for (int q = 0; q < 4; ++q) mma_bf16(d[q], afr[q][ks], rb[ks]);

        const float* xbf = xbuf + (s % 3) * XB_BUFSZ + (2 * tig) * XB_STRIDE + 16 * wid + gid;
        float hv[4];
#pragma unroll
        for (int p = 0; p < 4; ++p) {
            const int xo = (p & 1) * XB_STRIDE + 8 * (p >> 1);
            float gi = d[0][p] + xbf[xo];
            float gf = d[1][p] + xbf[xo + 128];
            float gg = d[2][p] + xbf[xo + 256];
            float go = d[3][p] + xbf[xo + 384];
            float cn = sig_fast(gf) * cst[p] + sig_fast(gi) * tanh_fast(gg);
            cst[p] = cn;
            hv[p] = sig_fast(go) * tanh_fast(cn);
        }

        const int r0 = 16 * wid + gid;
        hbuf[((s + 1) & 1) * 512 + r0 * 4 + tig]       = bf2(hv[0], hv[1]);
        hbuf[((s + 1) & 1) * 512 + (r0 + 8) * 4 + tig] = bf2(hv[2], hv[3]);

        const size_t orow = ((size_t)l * B_N + b0 + 2 * tig) * 256;
        hout[orow + r0]           = hv[0];
        hout[orow + 256 + r0]     = hv[1];
        hout[orow + r0 + 8]       = hv[2];
        hout[orow + 256 + r0 + 8] = hv[3];

        if (s + 2 < L_SEQ) {
            asm volatile("cp.async.wait_group 1;");
        } else {
            asm volatile("cp.async.wait_group 0;");
        }
        __syncthreads();
    }
}

// ============================================================================
// Kernel 3: emis via HMMA. M=128 rows, N=48 tags, K=256.
// ============================================================================
#define EMM_A_OFF    0
#define EMM_B_OFF    (128 * 264 * 2)
#define EMM_BIAS_OFF (EMM_B_OFF + 48 * 264 * 2)
#define EMM_SMEM     (EMM_BIAS_OFF + 48 * 4)

__global__ __launch_bounds__(256) void emis_mma_kernel(const float* __restrict__ Wout,
                                                       const float* __restrict__ bout) {
    extern __shared__ char esm[];
    __nv_bfloat16* A_s = (__nv_bfloat16*)(esm + EMM_A_OFF);   // [128][264]
    __nv_bfloat16* B_s = (__nv_bfloat16*)(esm + EMM_B_OFF);   // [48][264]
    float* bias_s      = (float*)(esm + EMM_BIAS_OFF);        // [48]

    const int tid = threadIdx.x;
    const int row0 = blockIdx.x * 128;

    if (tid < 48) bias_s[tid] = bout[tid];

    // A: hcat rows -> bf16
    {
        const int r = tid >> 1, hf = tid & 1;
        const float4* src = (const float4*)(g_hcat + (size_t)(row0 + r) * 256 + hf * 128);
        __nv_bfloat16* dst = A_s + r * 264 + hf * 128;
#pragma unroll
        for (int i = 0; i < 16; ++i) {
            float4 v0 = src[2 * i], v1 = src[2 * i + 1];
            uint4 pk;
            pk.x = bf2(v0.x, v0.y);
            pk.y = bf2(v0.z, v0.w);
            pk.z = bf2(v1.x, v1.y);
            pk.w = bf2(v1.z, v1.w);
            *(uint4*)(dst + i * 8) = pk;
        }
    }
    // B: Wout rows -> bf16
    if (tid < 96) {
        const int r = tid >> 1, hf = tid & 1;
        const float4* src = (const float4*)(Wout + (size_t)r * 256 + hf * 128);
        __nv_bfloat16* dst = B_s + r * 264 + hf * 128;
#pragma unroll
        for (int i = 0; i < 16; ++i) {
            float4 v0 = src[2 * i], v1 = src[2 * i + 1];
            uint4 pk;
            pk.x = bf2(v0.x, v0.y);
            pk.y = bf2(v0.z, v0.w);
            pk.z = bf2(v1.x, v1.y);
            pk.w = bf2(v1.z, v1.w);
            *(uint4*)(dst + i * 8) = pk;
        }
    }
    __syncthreads();

    const uint32_t As = smem_u32(A_s), Bs = smem_u32(B_s);
    const int lane = tid & 31, wid = tid >> 5;
    const int m_base = (wid >> 1) * 32;   // 4 m-warps x 32 rows
    const int n_base = (wid & 1) * 24;    // 2 n-warps x 24 tags

    const int aq = lane >> 3;
    const uint32_t a_row = (uint32_t)((aq & 1) * 8 + (lane & 7));
    const uint32_t a_col = (uint32_t)((aq >> 1) * 16);
    const uint32_t b_row = (uint32_t)(lane & 7);
    const uint32_t b_col = (uint32_t)(((lane >> 3) & 1) * 16);

    float d[2][3][4];
#pragma unroll
    for (int mt = 0; mt < 2; ++mt)
#pragma unroll
        for (int nt = 0; nt < 3; ++nt)
#pragma unroll
            for (int c = 0; c < 4; ++c) d[mt][nt][c] = 0.f;

#pragma unroll
    for (int ks = 0; ks < 16; ++ks) {
        uint32_t a0[4], a1[4];
        ldsm_x4(a0, As + (m_base + 0 + a_row) * 528 + ks * 32 + a_col);
        ldsm_x4(a1, As + (m_base + 16 + a_row) * 528 + ks * 32 + a_col);
#pragma unroll
        for (int nt = 0; nt < 3; ++nt) {
            uint32_t bb[2];
            ldsm_x2(bb, Bs + (n_base + nt * 8 + b_row) * 528 + ks * 32 + b_col);
            mma_bf16(d[0][nt], a0, bb);
            mma_bf16(d[1][nt], a1, bb);
        }
    }

    const int r = lane >> 2, c = (lane & 3) * 2;
#pragma unroll
    for (int mt = 0; mt < 2; ++mt) {
        const int gr = row0 + m_base + mt * 16 + r;
#pragma unroll
        for (int nt = 0; nt < 3; ++nt) {
            const int gc = n_base + nt * 8 + c;
            const float bx = bias_s[gc], by = bias_s[gc + 1];
            float2 o0 = make_float2(d[mt][nt][0] + bx, d[mt][nt][1] + by);
            float2 o1 = make_float2(d[mt][nt][2] + bx, d[mt][nt][3] + by);
            *(float2*)(g_emis + (size_t)gr * T_TAG + gc) = o0;
            *(float2*)(g_emis + (size_t)(gr + 8) * T_TAG + gc) = o1;
        }
    }
}

// ============================================================================
// Kernel 4: CRF — one WARP per sequence. Unnormalized forward vector with
// periodic renorm (every 4 steps): p'_j = (sum_i p_i E_ij) * e^{em_j},
// E = exp(trans) held as per-lane register columns. No per-step max.
// ============================================================================
__global__ __launch_bounds__(256) void crf_kernel(const int* __restrict__ words,
                                                  const int* __restrict__ tags,
                                                  const float* __restrict__ trans,
                                                  const float* __restrict__ start_trans,
                                                  const float* __restrict__ end_trans) {
    __shared__ __align__(16) float tr_s[48 * 48];
    __shared__ __align__(16) float p_s[8][48];

    const int tid = threadIdx.x;
    const int w = tid >> 5, lane = tid & 31;
    const int b = blockIdx.x * 8 + w;

    for (int i = tid; i < 48 * 48; i += 256) tr_s[i] = trans[i];
    __syncthreads();

    const int j1 = lane;
    const int j2 = 32 + lane;
    const bool has2 = lane < 16;

    // E columns in registers
    float e1[48], e2[48];
#pragma unroll
    for (int i = 0; i < 48; ++i) e1[i] = __expf(tr_s[i * 48 + j1]);
    if (has2) {
#pragma unroll
        for (int i = 0; i < 48; ++i) e2[i] = __expf(tr_s[i * 48 + j2]);
    }

    // sequence length (prefix mask == words != 0)
    int cnt = 0;
    for (int l = lane; l < L_SEQ; l += 32) cnt += (words[b * L_SEQ + l] != 0) ? 1 : 0;
#pragma unroll
    for (int o = 16; o; o >>= 1) cnt += __shfl_xor_sync(0xFFFFFFFFu, cnt, o);
    const int len = cnt;

    // numerator partials (l = 1 .. len-1)
    float np = 0.f;
    for (int l = 1 + lane; l < len; l += 32) {
        int tp = tags[b * L_SEQ + l - 1];
        int tc = tags[b * L_SEQ + l];
        np += tr_s[tp * 48 + tc] + g_emis[((size_t)l * B_N + b) * T_TAG + tc];
    }
#pragma unroll
    for (int o = 16; o; o >>= 1) np += __shfl_xor_sync(0xFFFFFFFFu, np, o);

    // init forward vector (unnormalized): p_j = exp(start_j + em0_j)
    float p1 = __expf(start_trans[j1] + g_emis[(size_t)b * T_TAG + j1]);
    float p2 = has2 ? __expf(start_trans[j2] + g_emis[(size_t)b * T_TAG + j2]) : 0.f;
    float logZ = 0.f;

    p_s[w][j1] = p1;
    if (has2) p_s[w][j2] = p2;
    __syncwarp();

    float em1 = 0.f, em2 = 0.f;
    if (len > 1) {
        const size_t eb = ((size_t)1 * B_N + b) * T_TAG;
        em1 = g_emis[eb + j1];
        em2 = has2 ? g_emis[eb + j2] : 0.f;
    }

    for (int l = 1; l < len; ++l) {
        // prefetch next step's emissions
        float en1 = 0.f, en2 = 0.f;
        if (l + 1 < len) {
            const size_t eb = ((size_t)(l + 1) * B_N + b) * T_TAG;
            en1 = g_emis[eb + j1];
            en2 = has2 ? g_emis[eb + j2] : 0.f;
        }

        // matvec against register-resident E columns
        float a10 = 0.f, a11 = 0.f, a12 = 0.f, a13 = 0.f;
        float a20 = 0.f, a21 = 0.f, a22 = 0.f, a23 = 0.f;
        const float4* p4 = (const float4*)p_s[w];
#pragma unroll
        for (int i4 = 0; i4 < 12; ++i4) {
            float4 pv = p4[i4];
            a10 = fmaf(pv.x, e1[4 * i4 + 0], a10);
            a11 = fmaf(pv.y, e1[4 * i4 + 1], a11);
            a12 = fmaf(pv.z, e1[4 * i4 + 2], a12);
            a13 = fmaf(pv.w, e1[4 * i4 + 3], a13);
            if (has2) {
                a20 = fmaf(pv.x, e2[4 * i4 + 0], a20);
                a21 = fmaf(pv.y, e2[4 * i4 + 1], a21);
                a22 = fmaf(pv.z, e2[4 * i4 + 2], a22);
                a23 = fmaf(pv.w, e2[4 * i4 + 3], a23);
            }
        }
        p1 = ((a10 + a11) + (a12 + a13)) * __expf(em1);
        if (has2) p2 = ((a20 + a21) + (a22 + a23)) * __expf(em2);
        em1 = en1;
        em2 = en2;

        // periodic renormalization (keeps fp32 in range; moves mass to logZ)
        if ((l & 3) == 0) {
            float S = p1 + (has2 ? p2 : 0.f);
#pragma unroll
            for (int o = 16; o; o >>= 1) S += __shfl_xor_sync(0xFFFFFFFFu, S, o);
            float inv = 1.f / S;
            p1 *= inv;
            if (has2) p2 *= inv;
            logZ += __logf(S);
        }

        __syncwarp();   // WAR on p_s
        p_s[w][j1] = p1;
        if (has2) p_s[w][j2] = p2;
        __syncwarp();
    }

    // termination
    float S = p1 * __expf(end_trans[j1]) + (has2 ? p2 * __expf(end_trans[j2]) : 0.f);
#pragma unroll
    for (int o = 16; o; o >>= 1) S += __shfl_xor_sync(0xFFFFFFFFu, S, o);

    if (lane == 0) {
        float denom = logZ + __logf(S);
        int t0 = tags[b * L_SEQ + 0];
        int tlast = tags[b * L_SEQ + (len - 1)];
        float num = np + start_trans[t0] + g_emis[(size_t)b * T_TAG + t0] + end_trans[tlast];
        g_llh[b] = num - denom;
    }
}

// ============================================================================
// Kernel 5: final reduction -> out[0] = -mean(llh)
// ============================================================================
__global__ __launch_bounds__(256) void final_kernel(float* __restrict__ out) {
    __shared__ float red[256];
    int tid = threadIdx.x;
    red[tid] = g_llh[tid];
    __syncthreads();
    for (int s = 128; s > 0; s >>= 1) {
        if (tid < s) red[tid] += red[tid + s];
        __syncthreads();
    }
    if (tid == 0) out[0] = -red[0] / (float)B_N;
}

// ============================================================================
// launch
// ============================================================================
extern "C" void kernel_launch(void* const* d_in, const int* in_sizes, int n_in,
                              void* d_out, int out_size) {
    const int*   words  = (const int*)d_in[0];
    const int*   tags   = (const int*)d_in[1];
    // d_in[2] = mask (unused; derived from words != 0)
    const float* emb    = (const float*)d_in[3];
    const float* Wih_f  = (const float*)d_in[4];
    const float* Whh_f  = (const float*)d_in[5];
    const float* bih_f  = (const float*)d_in[6];
    const float* bhh_f  = (const float*)d_in[7];
    const float* Wih_b  = (const float*)d_in[8];
    const float* Whh_b  = (const float*)d_in[9];
    const float* bih_b  = (const float*)d_in[10];
    const float* bhh_b  = (const float*)d_in[11];
    const float* Wout   = (const float*)d_in[12];
    const float* bout   = (const float*)d_in[13];
    const float* trans  = (const float*)d_in[14];
    const float* st     = (const float*)d_in[15];
    const float* et     = (const float*)d_in[16];
    float* out = (float*)d_out;

    cudaFuncSetAttribute(xproj_mma_kernel, cudaFuncAttributeMaxDynamicSharedMemorySize,
                         XPM_SMEM);
    cudaFuncSetAttribute(lstm_mma_kernel, cudaFuncAttributeMaxDynamicSharedMemorySize,
                         LSTM_SMEM);
    cudaFuncSetAttribute(emis_mma_kernel, cudaFuncAttributeMaxDynamicSharedMemorySize,
                         EMM_SMEM);

    // 1) input projections via HMMA, A-tile reused across all 4 gate chunks
    xproj_mma_kernel<<<dim3((L_SEQ * B_N) / 128, 2), 256, XPM_SMEM>>>(
        words, emb, Wih_f, bih_f, bhh_f, Wih_b, bih_b, bhh_b);

    // 2) HMMA BiLSTM with cp.async x staging: 32 CTAs x 2 dirs
    lstm_mma_kernel<<<dim3(B_N / NB, 2), 256, LSTM_SMEM>>>(Whh_f, Whh_b);

    // 3) emissions via HMMA
    emis_mma_kernel<<<(L_SEQ * B_N) / 128, 256, EMM_SMEM>>>(Wout, bout);

    // 4) CRF: one warp per sequence, renorm-based forward algorithm
    crf_kernel<<<B_N / 8, 256>>>(words, tags, trans, st, et);

    // 5) reduce to scalar
    final_kernel<<<1, 256>>>(out);
}

// round 9
// speedup vs baseline: 1.4492x; 1.4492x over previous
#include <cuda_runtime.h>
#include <cuda_fp16.h>
#include <cuda_bf16.h>
#include <cstdint>

// ---------------- problem constants ----------------
#define L_SEQ 512
#define B_N   256
#define E_DIM 128
#define H_DIM 128
#define G4    512     // 4*H
#define T_TAG 48
#define NB    8       // batch lanes per LSTM CTA (mma N=8)

typedef unsigned long long ull;

// ---------------- scratch (device globals; no allocation allowed) ----------------
__device__ float g_xproj_f[(size_t)L_SEQ * B_N * G4];   // 256 MiB
__device__ float g_xproj_b[(size_t)L_SEQ * B_N * G4];   // 256 MiB
__device__ float g_hcat[(size_t)L_SEQ * B_N * 256];     // 128 MiB  [l][b][2H]
__device__ float g_emis[(size_t)L_SEQ * B_N * T_TAG];   // 24 MiB
__device__ float g_llh[B_N];

// ---------------- generic helpers ----------------
__device__ __forceinline__ float tanh_fast(float x) {
    float y;
    asm("tanh.approx.f32 %0, %1;" : "=f"(y) : "f"(x));
    return y;
}
__device__ __forceinline__ float sig_fast(float x) {
    return fmaf(0.5f, tanh_fast(0.5f * x), 0.5f);
}
__device__ __forceinline__ uint32_t smem_u32(const void* p) {
    uint32_t a;
    asm("{ .reg .u64 t; cvta.to.shared.u64 t, %1; cvt.u32.u64 %0, t; }" : "=r"(a) : "l"(p));
    return a;
}
__device__ __forceinline__ uint32_t bf2(float x, float y) {
    __nv_bfloat162 t = __floats2bfloat162_rn(x, y);
    return *(uint32_t*)&t;
}
__device__ __forceinline__ void mma_bf16(float* d, const uint32_t* a, const uint32_t* b) {
    asm volatile(
        "mma.sync.aligned.m16n8k16.row.col.f32.bf16.bf16.f32 "
        "{%0,%1,%2,%3}, {%4,%5,%6,%7}, {%8,%9}, {%0,%1,%2,%3};"
        : "+f"(d[0]), "+f"(d[1]), "+f"(d[2]), "+f"(d[3])
        : "r"(a[0]), "r"(a[1]), "r"(a[2]), "r"(a[3]), "r"(b[0]), "r"(b[1]));
}
__device__ __forceinline__ void ldmatrix_x2_trans(uint32_t* r, uint32_t addr) {
    asm volatile("ldmatrix.sync.aligned.m8n8.x2.trans.shared.b16 {%0,%1}, [%2];"
                 : "=r"(r[0]), "=r"(r[1]) : "r"(addr));
}
__device__ __forceinline__ void ldsm_x4(uint32_t* r, uint32_t a) {
    asm volatile("ldmatrix.sync.aligned.m8n8.x4.shared.b16 {%0,%1,%2,%3}, [%4];"
                 : "=r"(r[0]), "=r"(r[1]), "=r"(r[2]), "=r"(r[3]) : "r"(a));
}
__device__ __forceinline__ void ldsm_x2(uint32_t* r, uint32_t a) {
    asm volatile("ldmatrix.sync.aligned.m8n8.x2.shared.b16 {%0,%1}, [%2];"
                 : "=r"(r[0]), "=r"(r[1]) : "r"(a));
}
__device__ __forceinline__ void cp16(uint32_t dst, const void* src) {
    asm volatile("cp.async.ca.shared.global [%0], [%1], 16;" :: "r"(dst), "l"(src));
}
__device__ __forceinline__ float warp_sum(float v) {
#pragma unroll
    for (int o = 16; o; o >>= 1) v += __shfl_xor_sync(0xFFFFFFFFu, v, o);
    return v;
}

// ============================================================================
// Kernel 1: xproj = emb[words] @ Wih^T + (bih+bhh) via HMMA bf16.
// CTA tile: 128 rows x 128 gates, K=128 (R7 grid-parallel form).
// ============================================================================
#define XPM_A_OFF    0
#define XPM_B_OFF    (128 * 136 * 2)
#define XPM_BIAS_OFF (2 * 128 * 136 * 2)
#define XPM_SMEM     (XPM_BIAS_OFF + 128 * 4)

__global__ __launch_bounds__(256) void xproj_mma_kernel(
    const int* __restrict__ words, const float* __restrict__ emb,
    const float* __restrict__ Wih_f, const float* __restrict__ bih_f,
    const float* __restrict__ bhh_f, const float* __restrict__ Wih_b,
    const float* __restrict__ bih_b, const float* __restrict__ bhh_b) {
    extern __shared__ char xsm[];
    __nv_bfloat16* A_s = (__nv_bfloat16*)(xsm + XPM_A_OFF);   // [128][136]
    __nv_bfloat16* B_s = (__nv_bfloat16*)(xsm + XPM_B_OFF);   // [128][136]
    float* bias_s      = (float*)(xsm + XPM_BIAS_OFF);        // [128]

    const int dir = blockIdx.z;
    const float* Wih = dir ? Wih_b : Wih_f;
    const float* b1  = dir ? bih_b : bih_f;
    const float* b2  = dir ? bhh_b : bhh_f;
    float* out       = dir ? g_xproj_b : g_xproj_f;

    const int row0 = blockIdx.y * 128;
    const int n0   = blockIdx.x * 128;
    const int tid  = threadIdx.x;

    if (tid < 128) bias_s[tid] = b1[n0 + tid] + b2[n0 + tid];

    // A: gathered embedding rows -> bf16 [r][k], 136-elem row pad
    {
        const int r = tid >> 1, hf = tid & 1;
        const int grow = row0 + r;
        const int l = grow >> 8, b = grow & 255;
        const int w = words[b * L_SEQ + l];
        const float4* src = (const float4*)(emb + (size_t)w * E_DIM + hf * 64);
        __nv_bfloat16* dst = A_s + r * 136 + hf * 64;
#pragma unroll
        for (int i = 0; i < 8; ++i) {
            float4 v0 = src[2 * i], v1 = src[2 * i + 1];
            uint4 pk;
            pk.x = bf2(v0.x, v0.y);
            pk.y = bf2(v0.z, v0.w);
            pk.z = bf2(v1.x, v1.y);
            pk.w = bf2(v1.z, v1.w);
            *(uint4*)(dst + i * 8) = pk;
        }
    }
    // B: Wih rows (native [gate][k]) -> bf16 [n][k]
    {
        const int r = tid >> 1, hf = tid & 1;
        const float4* src = (const float4*)(Wih + (size_t)(n0 + r) * E_DIM + hf * 64);
        __nv_bfloat16* dst = B_s + r * 136 + hf * 64;
#pragma unroll
        for (int i = 0; i < 8; ++i) {
            float4 v0 = src[2 * i], v1 = src[2 * i + 1];
            uint4 pk;
            pk.x = bf2(v0.x, v0.y);
            pk.y = bf2(v0.z, v0.w);
            pk.z = bf2(v1.x, v1.y);
            pk.w = bf2(v1.z, v1.w);
            *(uint4*)(dst + i * 8) = pk;
        }
    }
    __syncthreads();

    const uint32_t As = smem_u32(A_s), Bs = smem_u32(B_s);
    const int lane = tid & 31, wid = tid >> 5;
    const int m_base = (wid >> 1) * 32;   // 4 m-warps
    const int n_base = (wid & 1) * 64;    // 2 n-warps

    float d[2][8][4];
#pragma unroll
    for (int mt = 0; mt < 2; ++mt)
#pragma unroll
        for (int nt = 0; nt < 8; ++nt)
#pragma unroll
            for (int c = 0; c < 4; ++c) d[mt][nt][c] = 0.f;

    const int aq = lane >> 3;
    const uint32_t a_row = (uint32_t)((aq & 1) * 8 + (lane & 7));
    const uint32_t a_col = (uint32_t)((aq >> 1) * 16);
    const uint32_t b_row = (uint32_t)(lane & 7);
    const uint32_t b_col = (uint32_t)(((lane >> 3) & 1) * 16);

#pragma unroll
    for (int ks = 0; ks < 8; ++ks) {
        uint32_t a0[4], a1[4];
        ldsm_x4(a0, As + (m_base + 0 + a_row) * 272 + ks * 32 + a_col);
        ldsm_x4(a1, As + (m_base + 16 + a_row) * 272 + ks * 32 + a_col);
#pragma unroll
        for (int nt = 0; nt < 8; ++nt) {
            uint32_t bb[2];
            ldsm_x2(bb, Bs + (n_base + nt * 8 + b_row) * 272 + ks * 32 + b_col);
            mma_bf16(d[0][nt], a0, bb);
            mma_bf16(d[1][nt], a1, bb);
        }
    }

    const int r = lane >> 2, c = (lane & 3) * 2;
#pragma unroll
    for (int mt = 0; mt < 2; ++mt) {
        const int gr = row0 + m_base + mt * 16 + r;
#pragma unroll
        for (int nt = 0; nt < 8; ++nt) {
            const int gc = n_base + nt * 8 + c;
            const float bx = bias_s[gc], by = bias_s[gc + 1];
            float2 o0 = make_float2(d[mt][nt][0] + bx, d[mt][nt][1] + by);
            float2 o1 = make_float2(d[mt][nt][2] + bx, d[mt][nt][3] + by);
            *(float2*)(out + (size_t)gr * G4 + n0 + gc) = o0;
            *(float2*)(out + (size_t)(gr + 8) * G4 + n0 + gc) = o1;
        }
    }
}

// ============================================================================
// Kernel 2: HMMA LSTM. 256 threads, 8 batch/CTA, Whh A-frags in registers.
// xproj staged via cp.async 3-buffer pipeline. (unchanged)
// ============================================================================
#define LSTM_HBUF   0
#define LSTM_XBUF   4096
#define LSTM_SMEM   (4096 + 3 * 8 * 516 * 4)
#define XB_STRIDE   516
#define XB_BUFSZ    (8 * XB_STRIDE)

__global__ __launch_bounds__(256) void lstm_mma_kernel(const float* __restrict__ Whh_f,
                                                       const float* __restrict__ Whh_b) {
    extern __shared__ char smraw[];
    uint32_t* hbuf = (uint32_t*)(smraw + LSTM_HBUF);   // [2][128][4 bf16x2]
    float* xbuf    = (float*)(smraw + LSTM_XBUF);      // [3][8][516]

    const int tid  = threadIdx.x;
    const int lane = tid & 31;
    const int wid  = tid >> 5;
    const int gid  = lane >> 2;
    const int tig  = lane & 3;
    const int dir  = blockIdx.y;
    const int b0   = blockIdx.x * NB;
    const float* Whh = dir ? Whh_b : Whh_f;
    const float* xp  = dir ? g_xproj_b : g_xproj_f;
    float* hout      = g_hcat + dir * 128;

    const uint32_t hb_u32 = smem_u32(hbuf);
    const uint32_t xb_u32 = smem_u32(xbuf);

    uint32_t afr[4][8][4];
#pragma unroll
    for (int q = 0; q < 4; ++q) {
        const int r0 = 16 * wid + 128 * q + gid;
#pragma unroll
        for (int ks = 0; ks < 8; ++ks) {
            const int cc = ks * 16 + 2 * tig;
            float2 v00 = *(const float2*)(Whh + (size_t)r0 * 128 + cc);
            float2 v10 = *(const float2*)(Whh + (size_t)(r0 + 8) * 128 + cc);
            float2 v01 = *(const float2*)(Whh + (size_t)r0 * 128 + cc + 8);
            float2 v11 = *(const float2*)(Whh + (size_t)(r0 + 8) * 128 + cc + 8);
            afr[q][ks][0] = bf2(v00.x, v00.y);
            afr[q][ks][1] = bf2(v10.x, v10.y);
            afr[q][ks][2] = bf2(v01.x, v01.y);
            afr[q][ks][3] = bf2(v11.x, v11.y);
        }
    }

    for (int i = tid; i < 2 * 128 * 4; i += 256) hbuf[i] = 0;

#pragma unroll
    for (int ps = 0; ps < 2; ++ps) {
        const int l = dir ? (L_SEQ - 1 - ps) : ps;
        const float* src = xp + ((size_t)l * B_N + b0) * G4;
#pragma unroll
        for (int rr = 0; rr < 4; ++rr) {
            int idx = tid + rr * 256;
            int brow = idx >> 7, c16 = idx & 127;
            cp16(xb_u32 + (uint32_t)(ps * XB_BUFSZ * 4 + brow * XB_STRIDE * 4 + c16 * 16),
                 src + brow * 512 + c16 * 4);
        }
        asm volatile("cp.async.commit_group;");
    }
    asm volatile("cp.async.wait_group 1;");
    __syncthreads();

    float cst[4] = {0.f, 0.f, 0.f, 0.f};

    for (int s = 0; s < L_SEQ; ++s) {
        const int l = dir ? (L_SEQ - 1 - s) : s;

        if (s + 2 < L_SEQ) {
            const int lf = dir ? (L_SEQ - 3 - s) : (s + 2);
            const float* src = xp + ((size_t)lf * B_N + b0) * G4;
            const uint32_t dbase = xb_u32 + (uint32_t)(((s + 2) % 3) * XB_BUFSZ * 4);
#pragma unroll
            for (int rr = 0; rr < 4; ++rr) {
                int idx = tid + rr * 256;
                int brow = idx >> 7, c16 = idx & 127;
                cp16(dbase + (uint32_t)(brow * XB_STRIDE * 4 + c16 * 16),
                     src + brow * 512 + c16 * 4);
            }
            asm volatile("cp.async.commit_group;");
        }

        uint32_t rb[8][2];
        const uint32_t base = hb_u32 + (uint32_t)((s & 1) * 2048) + ((uint32_t)(lane & 15) << 4);
#pragma unroll
        for (int ks = 0; ks < 8; ++ks) ldmatrix_x2_trans(rb[ks], base + ks * 256);

        float d[4][4];
#pragma unroll
        for (int q = 0; q < 4; ++q)
#pragma unroll
            for (int c = 0; c < 4; ++c) d[q][c] = 0.f;
#pragma unroll
        for (int ks = 0; ks < 8; ++ks)
#pragma unroll
            for (int q = 0; q < 4; ++q) mma_bf16(d[q], afr[q][ks], rb[ks]);

        const float* xbf = xbuf + (s % 3) * XB_BUFSZ + (2 * tig) * XB_STRIDE + 16 * wid + gid;
        float hv[4];
#pragma unroll
        for (int p = 0; p < 4; ++p) {
            const int xo = (p & 1) * XB_STRIDE + 8 * (p >> 1);
            float gi = d[0][p] + xbf[xo];
            float gf = d[1][p] + xbf[xo + 128];
            float gg = d[2][p] + xbf[xo + 256];
            float go = d[3][p] + xbf[xo + 384];
            float cn = sig_fast(gf) * cst[p] + sig_fast(gi) * tanh_fast(gg);
            cst[p] = cn;
            hv[p] = sig_fast(go) * tanh_fast(cn);
        }

        const int r0 = 16 * wid + gid;
        hbuf[((s + 1) & 1) * 512 + r0 * 4 + tig]       = bf2(hv[0], hv[1]);
        hbuf[((s + 1) & 1) * 512 + (r0 + 8) * 4 + tig] = bf2(hv[2], hv[3]);

        const size_t orow = ((size_t)l * B_N + b0 + 2 * tig) * 256;
        hout[orow + r0]           = hv[0];
        hout[orow + 256 + r0]     = hv[1];
        hout[orow + r0 + 8]       = hv[2];
        hout[orow + 256 + r0 + 8] = hv[3];

        if (s + 2 < L_SEQ) {
            asm volatile("cp.async.wait_group 1;");
        } else {
            asm volatile("cp.async.wait_group 0;");
        }
        __syncthreads();
    }
}

// ============================================================================
// Kernel 3: emis via HMMA. M=128 rows, N=48 tags, K=256. (unchanged)
// ============================================================================
#define EMM_A_OFF    0
#define EMM_B_OFF    (128 * 264 * 2)
#define EMM_BIAS_OFF (EMM_B_OFF + 48 * 264 * 2)
#define EMM_SMEM     (EMM_BIAS_OFF + 48 * 4)

__global__ __launch_bounds__(256) void emis_mma_kernel(const float* __restrict__ Wout,
                                                       const float* __restrict__ bout) {
    extern __shared__ char esm[];
    __nv_bfloat16* A_s = (__nv_bfloat16*)(esm + EMM_A_OFF);   // [128][264]
    __nv_bfloat16* B_s = (__nv_bfloat16*)(esm + EMM_B_OFF);   // [48][264]
    float* bias_s      = (float*)(esm + EMM_BIAS_OFF);        // [48]

    const int tid = threadIdx.x;
    const int row0 = blockIdx.x * 128;

    if (tid < 48) bias_s[tid] = bout[tid];

    {
        const int r = tid >> 1, hf = tid & 1;
        const float4* src = (const float4*)(g_hcat + (size_t)(row0 + r) * 256 + hf * 128);
        __nv_bfloat16* dst = A_s + r * 264 + hf * 128;
#pragma unroll
        for (int i = 0; i < 16; ++i) {
            float4 v0 = src[2 * i], v1 = src[2 * i + 1];
            uint4 pk;
            pk.x = bf2(v0.x, v0.y);
            pk.y = bf2(v0.z, v0.w);
            pk.z = bf2(v1.x, v1.y);
            pk.w = bf2(v1.z, v1.w);
            *(uint4*)(dst + i * 8) = pk;
        }
    }
    if (tid < 96) {
        const int r = tid >> 1, hf = tid & 1;
        const float4* src = (const float4*)(Wout + (size_t)r * 256 + hf * 128);
        __nv_bfloat16* dst = B_s + r * 264 + hf * 128;
#pragma unroll
        for (int i = 0; i < 16; ++i) {
            float4 v0 = src[2 * i], v1 = src[2 * i + 1];
            uint4 pk;
            pk.x = bf2(v0.x, v0.y);
            pk.y = bf2(v0.z, v0.w);
            pk.z = bf2(v1.x, v1.y);
            pk.w = bf2(v1.z, v1.w);
            *(uint4*)(dst + i * 8) = pk;
        }
    }
    __syncthreads();

    const uint32_t As = smem_u32(A_s), Bs = smem_u32(B_s);
    const int lane = tid & 31, wid = tid >> 5;
    const int m_base = (wid >> 1) * 32;
    const int n_base = (wid & 1) * 24;

    const int aq = lane >> 3;
    const uint32_t a_row = (uint32_t)((aq & 1) * 8 + (lane & 7));
    const uint32_t a_col = (uint32_t)((aq >> 1) * 16);
    const uint32_t b_row = (uint32_t)(lane & 7);
    const uint32_t b_col = (uint32_t)(((lane >> 3) & 1) * 16);

    float d[2][3][4];
#pragma unroll
    for (int mt = 0; mt < 2; ++mt)
#pragma unroll
        for (int nt = 0; nt < 3; ++nt)
#pragma unroll
            for (int c = 0; c < 4; ++c) d[mt][nt][c] = 0.f;

#pragma unroll
    for (int ks = 0; ks < 16; ++ks) {
        uint32_t a0[4], a1[4];
        ldsm_x4(a0, As + (m_base + 0 + a_row) * 528 + ks * 32 + a_col);
        ldsm_x4(a1, As + (m_base + 16 + a_row) * 528 + ks * 32 + a_col);
#pragma unroll
        for (int nt = 0; nt < 3; ++nt) {
            uint32_t bb[2];
            ldsm_x2(bb, Bs + (n_base + nt * 8 + b_row) * 528 + ks * 32 + b_col);
            mma_bf16(d[0][nt], a0, bb);
            mma_bf16(d[1][nt], a1, bb);
        }
    }

    const int r = lane >> 2, c = (lane & 3) * 2;
#pragma unroll
    for (int mt = 0; mt < 2; ++mt) {
        const int gr = row0 + m_base + mt * 16 + r;
#pragma unroll
        for (int nt = 0; nt < 3; ++nt) {
            const int gc = n_base + nt * 8 + c;
            const float bx = bias_s[gc], by = bias_s[gc + 1];
            float2 o0 = make_float2(d[mt][nt][0] + bx, d[mt][nt][1] + by);
            float2 o1 = make_float2(d[mt][nt][2] + bx, d[mt][nt][3] + by);
            *(float2*)(g_emis + (size_t)gr * T_TAG + gc) = o0;
            *(float2*)(g_emis + (size_t)(gr + 8) * T_TAG + gc) = o1;
        }
    }
}

// ============================================================================
// Kernel 4: CRF — fwd/bwd split: 2 warps per sequence (even wid = forward to
// midpoint c, odd wid = backward to c). Z = sum_j alpha_c(j)*beta_c(j).
// Unnormalized vectors + renorm every 4 steps; E (and E^T) in smem, coalesced.
// 512 threads = 8 sequences per CTA; grid = 32.
// ============================================================================
__global__ __launch_bounds__(512) void crf_kernel(const int* __restrict__ words,
                                                  const int* __restrict__ tags,
                                                  const float* __restrict__ trans,
                                                  const float* __restrict__ start_trans,
                                                  const float* __restrict__ end_trans) {
    __shared__ __align__(16) float E_s[48 * 48];    // exp(trans)[i*48+j]
    __shared__ __align__(16) float ET_s[48 * 48];   // exp(trans)[i][j] at [j*48+i]
    __shared__ __align__(16) float tr_s[48 * 48];   // raw trans
    __shared__ __align__(16) float x_s[16][48];     // per-warp work vector
    __shared__ float lz_s[16];
    __shared__ float np_s[16];

    const int tid = threadIdx.x;
    const int wid = tid >> 5, lane = tid & 31;
    const int role = wid & 1;            // 0 = forward, 1 = backward
    const int b = blockIdx.x * 8 + (wid >> 1);

    for (int i = tid; i < 48 * 48; i += 512) {
        float v = trans[i];
        tr_s[i] = v;
        float e = __expf(v);
        E_s[i] = e;
        ET_s[(i % 48) * 48 + (i / 48)] = e;
    }
    __syncthreads();

    // sequence length (prefix mask == words != 0)
    int cnt = 0;
    for (int l = lane; l < L_SEQ; l += 32) cnt += (words[b * L_SEQ + l] != 0) ? 1 : 0;
#pragma unroll
    for (int o = 16; o; o >>= 1) cnt += __shfl_xor_sync(0xFFFFFFFFu, cnt, o);
    const int len = cnt;
    const int c = len >> 1;

    const int j1 = lane;
    const int j2 = 32 + lane;
    const bool has2 = lane < 16;
    const float* M = role ? ET_s : E_s;

    // ---- numerator partial: fwd covers l in [1, c], bwd covers [c+1, len-1] + end
    {
        const int lo = role ? (c + 1) : 1;
        const int hi = role ? len : (c + 1);
        float np = 0.f;
        for (int l = lo + lane; l < hi; l += 32) {
            int tp = tags[b * L_SEQ + l - 1];
            int tc = tags[b * L_SEQ + l];
            np += tr_s[tp * 48 + tc] + g_emis[((size_t)l * B_N + b) * T_TAG + tc];
        }
        np = warp_sum(np);
        if (lane == 0) {
            if (role == 0) {
                int t0 = tags[b * L_SEQ];
                np += start_trans[t0] + g_emis[(size_t)b * T_TAG + t0];
            } else {
                np += end_trans[tags[b * L_SEQ + (len - 1)]];
            }
            np_s[wid] = np;
        }
    }

    // ---- init vector ----
    float p1, p2, logZ = 0.f;
    if (role == 0) {
        p1 = __expf(start_trans[j1] + g_emis[(size_t)b * T_TAG + j1]);
        p2 = has2 ? __expf(start_trans[j2] + g_emis[(size_t)b * T_TAG + j2]) : 0.f;
    } else {
        p1 = __expf(end_trans[j1]);
        p2 = has2 ? __expf(end_trans[j2]) : 0.f;
    }

    const int nsteps = role ? (len - 1 - c) : c;

    // emission position for step t: fwd -> 1+t, bwd -> len-1-t
    // 2-deep prefetch pipeline
    float cu1 = 0.f, cu2 = 0.f, nx1 = 0.f, nx2 = 0.f;
    {
        if (nsteps > 0) {
            const int e0 = role ? (len - 1) : 1;
            const size_t eb = ((size_t)e0 * B_N + b) * T_TAG;
            cu1 = g_emis[eb + j1];
            cu2 = has2 ? g_emis[eb + j2] : 0.f;
        }
        if (nsteps > 1) {
            const int e1i = role ? (len - 2) : 2;
            const size_t eb = ((size_t)e1i * B_N + b) * T_TAG;
            nx1 = g_emis[eb + j1];
            nx2 = has2 ? g_emis[eb + j2] : 0.f;
        }
    }

    for (int t = 0; t < nsteps; ++t) {
        // prefetch emission for t+2
        float ft1 = 0.f, ft2 = 0.f;
        if (t + 2 < nsteps) {
            const int ei = role ? (len - 3 - t) : (3 + t);
            const size_t eb = ((size_t)ei * B_N + b) * T_TAG;
            ft1 = g_emis[eb + j1];
            ft2 = has2 ? g_emis[eb + j2] : 0.f;
        }

        // publish x: fwd -> raw p; bwd -> p * e^{em}
        float x1, x2;
        if (role == 0) {
            x1 = p1;
            x2 = p2;
        } else {
            x1 = p1 * __expf(cu1);
            x2 = has2 ? p2 * __expf(cu2) : 0.f;
        }
        x_s[wid][j1] = x1;
        if (has2) x_s[wid][j2] = x2;
        __syncwarp();

        // matvec: a_j = sum_k x_k * M[k*48 + j]
        float a10 = 0.f, a11 = 0.f, a12 = 0.f, a13 = 0.f;
        float a20 = 0.f, a21 = 0.f, a22 = 0.f, a23 = 0.f;
        const float4* p4 = (const float4*)x_s[wid];
#pragma unroll
        for (int i4 = 0; i4 < 12; ++i4) {
            float4 pv = p4[i4];
            const int i = i4 * 4;
            a10 = fmaf(pv.x, M[i * 48 + j1], a10);
            a11 = fmaf(pv.y, M[(i + 1) * 48 + j1], a11);
            a12 = fmaf(pv.z, M[(i + 2) * 48 + j1], a12);
            a13 = fmaf(pv.w, M[(i + 3) * 48 + j1], a13);
            if (has2) {
                a20 = fmaf(pv.x, M[i * 48 + j2], a20);
                a21 = fmaf(pv.y, M[(i + 1) * 48 + j2], a21);
                a22 = fmaf(pv.z, M[(i + 2) * 48 + j2], a22);
                a23 = fmaf(pv.w, M[(i + 3) * 48 + j2], a23);
            }
        }
        float s1 = (a10 + a11) + (a12 + a13);
        float s2 = (a20 + a21) + (a22 + a23);
        if (role == 0) {
            p1 = s1 * __expf(cu1);
            p2 = has2 ? s2 * __expf(cu2) : 0.f;
        } else {
            p1 = s1;
            p2 = has2 ? s2 : 0.f;
        }
        cu1 = nx1; cu2 = nx2;
        nx1 = ft1; nx2 = ft2;

        // periodic renormalization
        if ((t & 3) == 3) {
            float S = warp_sum(p1 + p2);
            float inv = 1.f / S;
            p1 *= inv;
            p2 *= inv;
            logZ += __logf(S);
        }
        __syncwarp();   // WAR on x_s
    }

    // publish final vector + scalars
    x_s[wid][j1] = p1;
    if (has2) x_s[wid][j2] = p2;
    if (lane == 0) lz_s[wid] = logZ;
    __syncthreads();

    // combine (forward warp of each pair)
    if (role == 0) {
        float dsum = x_s[wid][j1] * x_s[wid + 1][j1];
        if (has2) dsum += x_s[wid][j2] * x_s[wid + 1][j2];
        dsum = warp_sum(dsum);
        if (lane == 0) {
            float denom = lz_s[wid] + lz_s[wid + 1] + __logf(dsum);
            g_llh[b] = (np_s[wid] + np_s[wid + 1]) - denom;
        }
    }
}

// ============================================================================
// Kernel 5: final reduction -> out[0] = -mean(llh)
// ============================================================================
__global__ __launch_bounds__(256) void final_kernel(float* __restrict__ out) {
    __shared__ float red[256];
    int tid = threadIdx.x;
    red[tid] = g_llh[tid];
    __syncthreads();
    for (int s = 128; s > 0; s >>= 1) {
        if (tid < s) red[tid] += red[tid + s];
        __syncthreads();
    }
    if (tid == 0) out[0] = -red[0] / (float)B_N;
}

// ============================================================================
// launch
// ============================================================================
extern "C" void kernel_launch(void* const* d_in, const int* in_sizes, int n_in,
                              void* d_out, int out_size) {
    const int*   words  = (const int*)d_in[0];
    const int*   tags   = (const int*)d_in[1];
    // d_in[2] = mask (unused; derived from words != 0)
    const float* emb    = (const float*)d_in[3];
    const float* Wih_f  = (const float*)d_in[4];
    const float* Whh_f  = (const float*)d_in[5];
    const float* bih_f  = (const float*)d_in[6];
    const float* bhh_f  = (const float*)d_in[7];
    const float* Wih_b  = (const float*)d_in[8];
    const float* Whh_b  = (const float*)d_in[9];
    const float* bih_b  = (const float*)d_in[10];
    const float* bhh_b  = (const float*)d_in[11];
    const float* Wout   = (const float*)d_in[12];
    const float* bout   = (const float*)d_in[13];
    const float* trans  = (const float*)d_in[14];
    const float* st     = (const float*)d_in[15];
    const float* et     = (const float*)d_in[16];
    float* out = (float*)d_out;

    cudaFuncSetAttribute(xproj_mma_kernel, cudaFuncAttributeMaxDynamicSharedMemorySize,
                         XPM_SMEM);
    cudaFuncSetAttribute(lstm_mma_kernel, cudaFuncAttributeMaxDynamicSharedMemorySize,
                         LSTM_SMEM);
    cudaFuncSetAttribute(emis_mma_kernel, cudaFuncAttributeMaxDynamicSharedMemorySize,
                         EMM_SMEM);

    // 1) input projections via HMMA (grid-parallel R7 form)
    xproj_mma_kernel<<<dim3(4, (L_SEQ * B_N) / 128, 2), 256, XPM_SMEM>>>(
        words, emb, Wih_f, bih_f, bhh_f, Wih_b, bih_b, bhh_b);

    // 2) HMMA BiLSTM with cp.async x staging: 32 CTAs x 2 dirs
    lstm_mma_kernel<<<dim3(B_N / NB, 2), 256, LSTM_SMEM>>>(Whh_f, Whh_b);

    // 3) emissions via HMMA
    emis_mma_kernel<<<(L_SEQ * B_N) / 128, 256, EMM_SMEM>>>(Wout, bout);

    // 4) CRF: fwd/bwd split, 2 warps per sequence
    crf_kernel<<<B_N / 8, 512>>>(words, tags, trans, st, et);

    // 5) reduce to scalar
    final_kernel<<<1, 256>>>(out);
}

// round 10
// speedup vs baseline: 1.6867x; 1.1639x over previous
#include <cuda_runtime.h>
#include <cuda_fp16.h>
#include <cuda_bf16.h>
#include <cstdint>

// ---------------- problem constants ----------------
#define L_SEQ 512
#define B_N   256
#define E_DIM 128
#define H_DIM 128
#define G4    512     // 4*H
#define T_TAG 48
#define NB    8       // batch lanes per LSTM CTA (mma N=8)

typedef unsigned long long ull;

// ---------------- scratch (device globals; no allocation allowed) ----------------
__device__ __nv_bfloat16 g_xproj_f[(size_t)L_SEQ * B_N * G4];   // 128 MiB
__device__ __nv_bfloat16 g_xproj_b[(size_t)L_SEQ * B_N * G4];   // 128 MiB
__device__ __nv_bfloat16 g_hcat[(size_t)L_SEQ * B_N * 256];     // 64 MiB [l][b][2H]
__device__ float g_emis[(size_t)L_SEQ * B_N * T_TAG];           // 24 MiB
__device__ float g_llh[B_N];

// ---------------- generic helpers ----------------
__device__ __forceinline__ float tanh_fast(float x) {
    float y;
    asm("tanh.approx.f32 %0, %1;" : "=f"(y) : "f"(x));
    return y;
}
__device__ __forceinline__ float sig_fast(float x) {
    return fmaf(0.5f, tanh_fast(0.5f * x), 0.5f);
}
__device__ __forceinline__ uint32_t smem_u32(const void* p) {
    uint32_t a;
    asm("{ .reg .u64 t; cvta.to.shared.u64 t, %1; cvt.u32.u64 %0, t; }" : "=r"(a) : "l"(p));
    return a;
}
__device__ __forceinline__ uint32_t bf2(float x, float y) {
    __nv_bfloat162 t = __floats2bfloat162_rn(x, y);
    return *(uint32_t*)&t;
}
__device__ __forceinline__ void mma_bf16(float* d, const uint32_t* a, const uint32_t* b) {
    asm volatile(
        "mma.sync.aligned.m16n8k16.row.col.f32.bf16.bf16.f32 "
        "{%0,%1,%2,%3}, {%4,%5,%6,%7}, {%8,%9}, {%0,%1,%2,%3};"
        : "+f"(d[0]), "+f"(d[1]), "+f"(d[2]), "+f"(d[3])
        : "r"(a[0]), "r"(a[1]), "r"(a[2]), "r"(a[3]), "r"(b[0]), "r"(b[1]));
}
__device__ __forceinline__ void ldmatrix_x2_trans(uint32_t* r, uint32_t addr) {
    asm volatile("ldmatrix.sync.aligned.m8n8.x2.trans.shared.b16 {%0,%1}, [%2];"
                 : "=r"(r[0]), "=r"(r[1]) : "r"(addr));
}
__device__ __forceinline__ void ldsm_x4(uint32_t* r, uint32_t a) {
    asm volatile("ldmatrix.sync.aligned.m8n8.x4.shared.b16 {%0,%1,%2,%3}, [%4];"
                 : "=r"(r[0]), "=r"(r[1]), "=r"(r[2]), "=r"(r[3]) : "r"(a));
}
__device__ __forceinline__ void ldsm_x2(uint32_t* r, uint32_t a) {
    asm volatile("ldmatrix.sync.aligned.m8n8.x2.shared.b16 {%0,%1}, [%2];"
                 : "=r"(r[0]), "=r"(r[1]) : "r"(a));
}
__device__ __forceinline__ void cp16(uint32_t dst, const void* src) {
    asm volatile("cp.async.ca.shared.global [%0], [%1], 16;" :: "r"(dst), "l"(src));
}
__device__ __forceinline__ float warp_sum(float v) {
#pragma unroll
    for (int o = 16; o; o >>= 1) v += __shfl_xor_sync(0xFFFFFFFFu, v, o);
    return v;
}

// ============================================================================
// Kernel 1: xproj = emb[words] @ Wih^T + (bih+bhh) via HMMA bf16, bf16 output.
// CTA tile: 128 rows x 128 gates, K=128.
// ============================================================================
#define XPM_A_OFF    0
#define XPM_B_OFF    (128 * 136 * 2)
#define XPM_BIAS_OFF (2 * 128 * 136 * 2)
#define XPM_SMEM     (XPM_BIAS_OFF + 128 * 4)

__global__ __launch_bounds__(256) void xproj_mma_kernel(
    const int* __restrict__ words, const float* __restrict__ emb,
    const float* __restrict__ Wih_f, const float* __restrict__ bih_f,
    const float* __restrict__ bhh_f, const float* __restrict__ Wih_b,
    const float* __restrict__ bih_b, const float* __restrict__ bhh_b) {
    extern __shared__ char xsm[];
    __nv_bfloat16* A_s = (__nv_bfloat16*)(xsm + XPM_A_OFF);   // [128][136]
    __nv_bfloat16* B_s = (__nv_bfloat16*)(xsm + XPM_B_OFF);   // [128][136]
    float* bias_s      = (float*)(xsm + XPM_BIAS_OFF);        // [128]

    const int dir = blockIdx.z;
    const float* Wih = dir ? Wih_b : Wih_f;
    const float* b1  = dir ? bih_b : bih_f;
    const float* b2  = dir ? bhh_b : bhh_f;
    __nv_bfloat16* out = dir ? g_xproj_b : g_xproj_f;

    const int row0 = blockIdx.y * 128;
    const int n0   = blockIdx.x * 128;
    const int tid  = threadIdx.x;

    if (tid < 128) bias_s[tid] = b1[n0 + tid] + b2[n0 + tid];

    // A: gathered embedding rows -> bf16 [r][k], 136-elem row pad
    {
        const int r = tid >> 1, hf = tid & 1;
        const int grow = row0 + r;
        const int l = grow >> 8, b = grow & 255;
        const int w = words[b * L_SEQ + l];
        const float4* src = (const float4*)(emb + (size_t)w * E_DIM + hf * 64);
        __nv_bfloat16* dst = A_s + r * 136 + hf * 64;
#pragma unroll
        for (int i = 0; i < 8; ++i) {
            float4 v0 = src[2 * i], v1 = src[2 * i + 1];
            uint4 pk;
            pk.x = bf2(v0.x, v0.y);
            pk.y = bf2(v0.z, v0.w);
            pk.z = bf2(v1.x, v1.y);
            pk.w = bf2(v1.z, v1.w);
            *(uint4*)(dst + i * 8) = pk;
        }
    }
    // B: Wih rows (native [gate][k]) -> bf16 [n][k]
    {
        const int r = tid >> 1, hf = tid & 1;
        const float4* src = (const float4*)(Wih + (size_t)(n0 + r) * E_DIM + hf * 64);
        __nv_bfloat16* dst = B_s + r * 136 + hf * 64;
#pragma unroll
        for (int i = 0; i < 8; ++i) {
            float4 v0 = src[2 * i], v1 = src[2 * i + 1];
            uint4 pk;
            pk.x = bf2(v0.x, v0.y);
            pk.y = bf2(v0.z, v0.w);
            pk.z = bf2(v1.x, v1.y);
            pk.w = bf2(v1.z, v1.w);
            *(uint4*)(dst + i * 8) = pk;
        }
    }
    __syncthreads();

    const uint32_t As = smem_u32(A_s), Bs = smem_u32(B_s);
    const int lane = tid & 31, wid = tid >> 5;
    const int m_base = (wid >> 1) * 32;   // 4 m-warps
    const int n_base = (wid & 1) * 64;    // 2 n-warps

    float d[2][8][4];
#pragma unroll
    for (int mt = 0; mt < 2; ++mt)
#pragma unroll
        for (int nt = 0; nt < 8; ++nt)
#pragma unroll
            for (int c = 0; c < 4; ++c) d[mt][nt][c] = 0.f;

    const int aq = lane >> 3;
    const uint32_t a_row = (uint32_t)((aq & 1) * 8 + (lane & 7));
    const uint32_t a_col = (uint32_t)((aq >> 1) * 16);
    const uint32_t b_row = (uint32_t)(lane & 7);
    const uint32_t b_col = (uint32_t)(((lane >> 3) & 1) * 16);

#pragma unroll
    for (int ks = 0; ks < 8; ++ks) {
        uint32_t a0[4], a1[4];
        ldsm_x4(a0, As + (m_base + 0 + a_row) * 272 + ks * 32 + a_col);
        ldsm_x4(a1, As + (m_base + 16 + a_row) * 272 + ks * 32 + a_col);
#pragma unroll
        for (int nt = 0; nt < 8; ++nt) {
            uint32_t bb[2];
            ldsm_x2(bb, Bs + (n_base + nt * 8 + b_row) * 272 + ks * 32 + b_col);
            mma_bf16(d[0][nt], a0, bb);
            mma_bf16(d[1][nt], a1, bb);
        }
    }

    const int r = lane >> 2, c = (lane & 3) * 2;
#pragma unroll
    for (int mt = 0; mt < 2; ++mt) {
        const int gr = row0 + m_base + mt * 16 + r;
#pragma unroll
        for (int nt = 0; nt < 8; ++nt) {
            const int gc = n_base + nt * 8 + c;
            const float bx = bias_s[gc], by = bias_s[gc + 1];
            *(uint32_t*)(out + (size_t)gr * G4 + n0 + gc) =
                bf2(d[mt][nt][0] + bx, d[mt][nt][1] + by);
            *(uint32_t*)(out + (size_t)(gr + 8) * G4 + n0 + gc) =
                bf2(d[mt][nt][2] + bx, d[mt][nt][3] + by);
        }
    }
}

// ============================================================================
// Kernel 2: HMMA LSTM. 256 threads, 8 batch/CTA, Whh A-frags in registers.
// xproj (bf16) staged via cp.async 3-buffer pipeline; hcat stored bf16.
// ============================================================================
#define LSTM_HBUF   0
#define LSTM_XBUF   4096
#define XB_STRIDE   520                       // bf16 units per batch row
#define XB_BUFSZ    (8 * XB_STRIDE)           // bf16 units per buffer
#define LSTM_SMEM   (4096 + 3 * XB_BUFSZ * 2)

__global__ __launch_bounds__(256) void lstm_mma_kernel(const float* __restrict__ Whh_f,
                                                       const float* __restrict__ Whh_b) {
    extern __shared__ char smraw[];
    uint32_t* hbuf      = (uint32_t*)(smraw + LSTM_HBUF);       // [2][128][4 bf16x2]
    __nv_bfloat16* xbuf = (__nv_bfloat16*)(smraw + LSTM_XBUF);  // [3][8][520]

    const int tid  = threadIdx.x;
    const int lane = tid & 31;
    const int wid  = tid >> 5;
    const int gid  = lane >> 2;
    const int tig  = lane & 3;
    const int dir  = blockIdx.y;
    const int b0   = blockIdx.x * NB;
    const float* Whh = dir ? Whh_b : Whh_f;
    const __nv_bfloat16* xp = dir ? g_xproj_b : g_xproj_f;
    __nv_bfloat16* hout     = g_hcat + dir * 128;

    const uint32_t hb_u32 = smem_u32(hbuf);
    const uint32_t xb_u32 = smem_u32(xbuf);

    uint32_t afr[4][8][4];
#pragma unroll
    for (int q = 0; q < 4; ++q) {
        const int r0 = 16 * wid + 128 * q + gid;
#pragma unroll
        for (int ks = 0; ks < 8; ++ks) {
            const int cc = ks * 16 + 2 * tig;
            float2 v00 = *(const float2*)(Whh + (size_t)r0 * 128 + cc);
            float2 v10 = *(const float2*)(Whh + (size_t)(r0 + 8) * 128 + cc);
            float2 v01 = *(const float2*)(Whh + (size_t)r0 * 128 + cc + 8);
            float2 v11 = *(const float2*)(Whh + (size_t)(r0 + 8) * 128 + cc + 8);
            afr[q][ks][0] = bf2(v00.x, v00.y);
            afr[q][ks][1] = bf2(v10.x, v10.y);
            afr[q][ks][2] = bf2(v01.x, v01.y);
            afr[q][ks][3] = bf2(v11.x, v11.y);
        }
    }

    for (int i = tid; i < 2 * 128 * 4; i += 256) hbuf[i] = 0;

    // prologue: prefetch x(0), x(1)  (512 x 16B per buffer = 2 cp16/thread)
#pragma unroll
    for (int ps = 0; ps < 2; ++ps) {
        const int l = dir ? (L_SEQ - 1 - ps) : ps;
        const __nv_bfloat16* src = xp + ((size_t)l * B_N + b0) * G4;
#pragma unroll
        for (int rr = 0; rr < 2; ++rr) {
            int idx = tid + rr * 256;           // 0..511
            int brow = idx >> 6, c16 = idx & 63;
            cp16(xb_u32 + (uint32_t)(ps * XB_BUFSZ * 2 + brow * XB_STRIDE * 2 + c16 * 16),
                 src + brow * 512 + c16 * 8);
        }
        asm volatile("cp.async.commit_group;");
    }
    asm volatile("cp.async.wait_group 1;");
    __syncthreads();

    float cst[4] = {0.f, 0.f, 0.f, 0.f};

    for (int s = 0; s < L_SEQ; ++s) {
        const int l = dir ? (L_SEQ - 1 - s) : s;

        if (s + 2 < L_SEQ) {
            const int lf = dir ? (L_SEQ - 3 - s) : (s + 2);
            const __nv_bfloat16* src = xp + ((size_t)lf * B_N + b0) * G4;
            const uint32_t dbase = xb_u32 + (uint32_t)(((s + 2) % 3) * XB_BUFSZ * 2);
#pragma unroll
            for (int rr = 0; rr < 2; ++rr) {
                int idx = tid + rr * 256;
                int brow = idx >> 6, c16 = idx & 63;
                cp16(dbase + (uint32_t)(brow * XB_STRIDE * 2 + c16 * 16),
                     src + brow * 512 + c16 * 8);
            }
            asm volatile("cp.async.commit_group;");
        }

        uint32_t rb[8][2];
        const uint32_t base = hb_u32 + (uint32_t)((s & 1) * 2048) + ((uint32_t)(lane & 15) << 4);
#pragma unroll
        for (int ks = 0; ks < 8; ++ks) ldmatrix_x2_trans(rb[ks], base + ks * 256);

        float d[4][4];
#pragma unroll
        for (int q = 0; q < 4; ++q)
#pragma unroll
            for (int c = 0; c < 4; ++c) d[q][c] = 0.f;
#pragma unroll
        for (int ks = 0; ks < 8; ++ks)
#pragma unroll
            for (int q = 0; q < 4; ++q) mma_bf16(d[q], afr[q][ks], rb[ks]);

        const __nv_bfloat16* xbf =
            xbuf + (s % 3) * XB_BUFSZ + (2 * tig) * XB_STRIDE + 16 * wid + gid;
        float hv[4];
#pragma unroll
        for (int p = 0; p < 4; ++p) {
            const int xo = (p & 1) * XB_STRIDE + 8 * (p >> 1);
            float gi = d[0][p] + __bfloat162float(xbf[xo]);
            float gf = d[1][p] + __bfloat162float(xbf[xo + 128]);
            float gg = d[2][p] + __bfloat162float(xbf[xo + 256]);
            float go = d[3][p] + __bfloat162float(xbf[xo + 384]);
            float cn = sig_fast(gf) * cst[p] + sig_fast(gi) * tanh_fast(gg);
            cst[p] = cn;
            hv[p] = sig_fast(go) * tanh_fast(cn);
        }

        const int r0 = 16 * wid + gid;
        hbuf[((s + 1) & 1) * 512 + r0 * 4 + tig]       = bf2(hv[0], hv[1]);
        hbuf[((s + 1) & 1) * 512 + (r0 + 8) * 4 + tig] = bf2(hv[2], hv[3]);

        const size_t orow = ((size_t)l * B_N + b0 + 2 * tig) * 256;
        hout[orow + r0]           = __float2bfloat16(hv[0]);
        hout[orow + 256 + r0]     = __float2bfloat16(hv[1]);
        hout[orow + r0 + 8]       = __float2bfloat16(hv[2]);
        hout[orow + 256 + r0 + 8] = __float2bfloat16(hv[3]);

        if (s + 2 < L_SEQ) {
            asm volatile("cp.async.wait_group 1;");
        } else {
            asm volatile("cp.async.wait_group 0;");
        }
        __syncthreads();
    }
}

// ============================================================================
// Kernel 3: emis via HMMA. M=128 rows, N=48 tags, K=256. hcat already bf16.
// ============================================================================
#define EMM_A_OFF    0
#define EMM_B_OFF    (128 * 264 * 2)
#define EMM_BIAS_OFF (EMM_B_OFF + 48 * 264 * 2)
#define EMM_SMEM     (EMM_BIAS_OFF + 48 * 4)

__global__ __launch_bounds__(256) void emis_mma_kernel(const float* __restrict__ Wout,
                                                       const float* __restrict__ bout) {
    extern __shared__ char esm[];
    __nv_bfloat16* A_s = (__nv_bfloat16*)(esm + EMM_A_OFF);   // [128][264]
    __nv_bfloat16* B_s = (__nv_bfloat16*)(esm + EMM_B_OFF);   // [48][264]
    float* bias_s      = (float*)(esm + EMM_BIAS_OFF);        // [48]

    const int tid = threadIdx.x;
    const int row0 = blockIdx.x * 128;

    if (tid < 48) bias_s[tid] = bout[tid];

    // A: hcat rows (bf16) -> straight copy
    {
        const int r = tid >> 1, hf = tid & 1;
        const uint4* src = (const uint4*)(g_hcat + (size_t)(row0 + r) * 256 + hf * 128);
        uint4* dst = (uint4*)(A_s + r * 264 + hf * 128);
#pragma unroll
        for (int i = 0; i < 16; ++i) dst[i] = src[i];
    }
    // B: Wout rows -> bf16
    if (tid < 96) {
        const int r = tid >> 1, hf = tid & 1;
        const float4* src = (const float4*)(Wout + (size_t)r * 256 + hf * 128);
        __nv_bfloat16* dst = B_s + r * 264 + hf * 128;
#pragma unroll
        for (int i = 0; i < 16; ++i) {
            float4 v0 = src[2 * i], v1 = src[2 * i + 1];
            uint4 pk;
            pk.x = bf2(v0.x, v0.y);
            pk.y = bf2(v0.z, v0.w);
            pk.z = bf2(v1.x, v1.y);
            pk.w = bf2(v1.z, v1.w);
            *(uint4*)(dst + i * 8) = pk;
        }
    }
    __syncthreads();

    const uint32_t As = smem_u32(A_s), Bs = smem_u32(B_s);
    const int lane = tid & 31, wid = tid >> 5;
    const int m_base = (wid >> 1) * 32;
    const int n_base = (wid & 1) * 24;

    const int aq = lane >> 3;
    const uint32_t a_row = (uint32_t)((aq & 1) * 8 + (lane & 7));
    const uint32_t a_col = (uint32_t)((aq >> 1) * 16);
    const uint32_t b_row = (uint32_t)(lane & 7);
    const uint32_t b_col = (uint32_t)(((lane >> 3) & 1) * 16);

    float d[2][3][4];
#pragma unroll
    for (int mt = 0; mt < 2; ++mt)
#pragma unroll
        for (int nt = 0; nt < 3; ++nt)
#pragma unroll
            for (int c = 0; c < 4; ++c) d[mt][nt][c] = 0.f;

#pragma unroll
    for (int ks = 0; ks < 16; ++ks) {
        uint32_t a0[4], a1[4];
        ldsm_x4(a0, As + (m_base + 0 + a_row) * 528 + ks * 32 + a_col);
        ldsm_x4(a1, As + (m_base + 16 + a_row) * 528 + ks * 32 + a_col);
#pragma unroll
        for (int nt = 0; nt < 3; ++nt) {
            uint32_t bb[2];
            ldsm_x2(bb, Bs + (n_base + nt * 8 + b_row) * 528 + ks * 32 + b_col);
            mma_bf16(d[0][nt], a0, bb);
            mma_bf16(d[1][nt], a1, bb);
        }
    }

    const int r = lane >> 2, c = (lane & 3) * 2;
#pragma unroll
    for (int mt = 0; mt < 2; ++mt) {
        const int gr = row0 + m_base + mt * 16 + r;
#pragma unroll
        for (int nt = 0; nt < 3; ++nt) {
            const int gc = n_base + nt * 8 + c;
            const float bx = bias_s[gc], by = bias_s[gc + 1];
            float2 o0 = make_float2(d[mt][nt][0] + bx, d[mt][nt][1] + by);
            float2 o1 = make_float2(d[mt][nt][2] + bx, d[mt][nt][3] + by);
            *(float2*)(g_emis + (size_t)gr * T_TAG + gc) = o0;
            *(float2*)(g_emis + (size_t)(gr + 8) * T_TAG + gc) = o1;
        }
    }
}

// ============================================================================
// Kernel 4: CRF — fwd/bwd split, 2 warps per sequence, now only 2 sequences
// per CTA (128 threads, 128 CTAs -> 1 CTA/SM, 1 warp/SMSP).
// ============================================================================
__global__ __launch_bounds__(128) void crf_kernel(const int* __restrict__ words,
                                                  const int* __restrict__ tags,
                                                  const float* __restrict__ trans,
                                                  const float* __restrict__ start_trans,
                                                  const float* __restrict__ end_trans) {
    __shared__ __align__(16) float E_s[48 * 48];    // exp(trans)[i*48+j]
    __shared__ __align__(16) float ET_s[48 * 48];   // exp(trans) transposed
    __shared__ __align__(16) float tr_s[48 * 48];   // raw trans
    __shared__ __align__(16) float x_s[4][48];      // per-warp work vector
    __shared__ float lz_s[4];
    __shared__ float np_s[4];

    const int tid = threadIdx.x;
    const int wid = tid >> 5, lane = tid & 31;
    const int role = wid & 1;            // 0 = forward, 1 = backward
    const int b = blockIdx.x * 2 + (wid >> 1);

    for (int i = tid; i < 48 * 48; i += 128) {
        float v = trans[i];
        tr_s[i] = v;
        float e = __expf(v);
        E_s[i] = e;
        ET_s[(i % 48) * 48 + (i / 48)] = e;
    }
    __syncthreads();

    // sequence length (prefix mask == words != 0)
    int cnt = 0;
    for (int l = lane; l < L_SEQ; l += 32) cnt += (words[b * L_SEQ + l] != 0) ? 1 : 0;
#pragma unroll
    for (int o = 16; o; o >>= 1) cnt += __shfl_xor_sync(0xFFFFFFFFu, cnt, o);
    const int len = cnt;
    const int c = len >> 1;

    const int j1 = lane;
    const int j2 = 32 + lane;
    const bool has2 = lane < 16;
    const float* M = role ? ET_s : E_s;

    // ---- numerator partial ----
    {
        const int lo = role ? (c + 1) : 1;
        const int hi = role ? len : (c + 1);
        float np = 0.f;
        for (int l = lo + lane; l < hi; l += 32) {
            int tp = tags[b * L_SEQ + l - 1];
            int tc = tags[b * L_SEQ + l];
            np += tr_s[tp * 48 + tc] + g_emis[((size_t)l * B_N + b) * T_TAG + tc];
        }
        np = warp_sum(np);
        if (lane == 0) {
            if (role == 0) {
                int t0 = tags[b * L_SEQ];
                np += start_trans[t0] + g_emis[(size_t)b * T_TAG + t0];
            } else {
                np += end_trans[tags[b * L_SEQ + (len - 1)]];
            }
            np_s[wid] = np;
        }
    }

    // ---- init vector ----
    float p1, p2, logZ = 0.f;
    if (role == 0) {
        p1 = __expf(start_trans[j1] + g_emis[(size_t)b * T_TAG + j1]);
        p2 = has2 ? __expf(start_trans[j2] + g_emis[(size_t)b * T_TAG + j2]) : 0.f;
    } else {
        p1 = __expf(end_trans[j1]);
        p2 = has2 ? __expf(end_trans[j2]) : 0.f;
    }

    const int nsteps = role ? (len - 1 - c) : c;

    float cu1 = 0.f, cu2 = 0.f, nx1 = 0.f, nx2 = 0.f;
    {
        if (nsteps > 0) {
            const int e0 = role ? (len - 1) : 1;
            const size_t eb = ((size_t)e0 * B_N + b) * T_TAG;
            cu1 = g_emis[eb + j1];
            cu2 = has2 ? g_emis[eb + j2] : 0.f;
        }
        if (nsteps > 1) {
            const int e1i = role ? (len - 2) : 2;
            const size_t eb = ((size_t)e1i * B_N + b) * T_TAG;
            nx1 = g_emis[eb + j1];
            nx2 = has2 ? g_emis[eb + j2] : 0.f;
        }
    }

    for (int t = 0; t < nsteps; ++t) {
        float ft1 = 0.f, ft2 = 0.f;
        if (t + 2 < nsteps) {
            const int ei = role ? (len - 3 - t) : (3 + t);
            const size_t eb = ((size_t)ei * B_N + b) * T_TAG;
            ft1 = g_emis[eb + j1];
            ft2 = has2 ? g_emis[eb + j2] : 0.f;
        }

        float x1, x2;
        if (role == 0) {
            x1 = p1;
            x2 = p2;
        } else {
            x1 = p1 * __expf(cu1);
            x2 = has2 ? p2 * __expf(cu2) : 0.f;
        }
        x_s[wid][j1] = x1;
        if (has2) x_s[wid][j2] = x2;
        __syncwarp();

        float a10 = 0.f, a11 = 0.f, a12 = 0.f, a13 = 0.f;
        float a20 = 0.f, a21 = 0.f, a22 = 0.f, a23 = 0.f;
        const float4* p4 = (const float4*)x_s[wid];
#pragma unroll
        for (int i4 = 0; i4 < 12; ++i4) {
            float4 pv = p4[i4];
            const int i = i4 * 4;
            a10 = fmaf(pv.x, M[i * 48 + j1], a10);
            a11 = fmaf(pv.y, M[(i + 1) * 48 + j1], a11);
            a12 = fmaf(pv.z, M[(i + 2) * 48 + j1], a12);
            a13 = fmaf(pv.w, M[(i + 3) * 48 + j1], a13);
            if (has2) {
                a20 = fmaf(pv.x, M[i * 48 + j2], a20);
                a21 = fmaf(pv.y, M[(i + 1) * 48 + j2], a21);
                a22 = fmaf(pv.z, M[(i + 2) * 48 + j2], a22);
                a23 = fmaf(pv.w, M[(i + 3) * 48 + j2], a23);
            }
        }
        float s1 = (a10 + a11) + (a12 + a13);
        float s2 = (a20 + a21) + (a22 + a23);
        if (role == 0) {
            p1 = s1 * __expf(cu1);
            p2 = has2 ? s2 * __expf(cu2) : 0.f;
        } else {
            p1 = s1;
            p2 = has2 ? s2 : 0.f;
        }
        cu1 = nx1; cu2 = nx2;
        nx1 = ft1; nx2 = ft2;

        if ((t & 3) == 3) {
            float S = warp_sum(p1 + p2);
            float inv = 1.f / S;
            p1 *= inv;
            p2 *= inv;
            logZ += __logf(S);
        }
        __syncwarp();
    }

    x_s[wid][j1] = p1;
    if (has2) x_s[wid][j2] = p2;
    if (lane == 0) lz_s[wid] = logZ;
    __syncthreads();

    if (role == 0) {
        float dsum = x_s[wid][j1] * x_s[wid + 1][j1];
        if (has2) dsum += x_s[wid][j2] * x_s[wid + 1][j2];
        dsum = warp_sum(dsum);
        if (lane == 0) {
            float denom = lz_s[wid] + lz_s[wid + 1] + __logf(dsum);
            g_llh[b] = (np_s[wid] + np_s[wid + 1]) - denom;
        }
    }
}

// ============================================================================
// Kernel 5: final reduction -> out[0] = -mean(llh)
// ============================================================================
__global__ __launch_bounds__(256) void final_kernel(float* __restrict__ out) {
    __shared__ float red[256];
    int tid = threadIdx.x;
    red[tid] = g_llh[tid];
    __syncthreads();
    for (int s = 128; s > 0; s >>= 1) {
        if (tid < s) red[tid] += red[tid + s];
        __syncthreads();
    }
    if (tid == 0) out[0] = -red[0] / (float)B_N;
}

// ============================================================================
// launch
// ============================================================================
extern "C" void kernel_launch(void* const* d_in, const int* in_sizes, int n_in,
                              void* d_out, int out_size) {
    const int*   words  = (const int*)d_in[0];
    const int*   tags   = (const int*)d_in[1];
    // d_in[2] = mask (unused; derived from words != 0)
    const float* emb    = (const float*)d_in[3];
    const float* Wih_f  = (const float*)d_in[4];
    const float* Whh_f  = (const float*)d_in[5];
    const float* bih_f  = (const float*)d_in[6];
    const float* bhh_f  = (const float*)d_in[7];
    const float* Wih_b  = (const float*)d_in[8];
    const float* Whh_b  = (const float*)d_in[9];
    const float* bih_b  = (const float*)d_in[10];
    const float* bhh_b  = (const float*)d_in[11];
    const float* Wout   = (const float*)d_in[12];
    const float* bout   = (const float*)d_in[13];
    const float* trans  = (const float*)d_in[14];
    const float* st     = (const float*)d_in[15];
    const float* et     = (const float*)d_in[16];
    float* out = (float*)d_out;

    cudaFuncSetAttribute(xproj_mma_kernel, cudaFuncAttributeMaxDynamicSharedMemorySize,
                         XPM_SMEM);
    cudaFuncSetAttribute(lstm_mma_kernel, cudaFuncAttributeMaxDynamicSharedMemorySize,
                         LSTM_SMEM);
    cudaFuncSetAttribute(emis_mma_kernel, cudaFuncAttributeMaxDynamicSharedMemorySize,
                         EMM_SMEM);

    // 1) input projections via HMMA (bf16 output)
    xproj_mma_kernel<<<dim3(4, (L_SEQ * B_N) / 128, 2), 256, XPM_SMEM>>>(
        words, emb, Wih_f, bih_f, bhh_f, Wih_b, bih_b, bhh_b);

    // 2) HMMA BiLSTM with cp.async x staging: 32 CTAs x 2 dirs
    lstm_mma_kernel<<<dim3(B_N / NB, 2), 256, LSTM_SMEM>>>(Whh_f, Whh_b);

    // 3) emissions via HMMA
    emis_mma_kernel<<<(L_SEQ * B_N) / 128, 256, EMM_SMEM>>>(Wout, bout);

    // 4) CRF: fwd/bwd split, 2 warps per sequence, 2 sequences per CTA
    crf_kernel<<<B_N / 2, 128>>>(words, tags, trans, st, et);

    // 5) reduce to scalar
    final_kernel<<<1, 256>>>(out);
}